// round 1
// baseline (speedup 1.0000x reference)
#include <cuda_runtime.h>
#include <cuda_bf16.h>

// Rank-based average pooling: 2x2 window, stride 2, mean of top-2 values.
// x: [16,128,128,256] f32 NHWC  ->  out: [16,64,64,256] f32
//
// Pure streaming kernel: each thread produces one float4 of output (4 channels),
// reading 4 float4s (the 2x2 window at those channels). All loads/stores are
// fully coalesced 16B accesses; warp covers 512B contiguous per region.

#define C4 64          // 256 channels / 4
#define WO 64
#define HO 64
#define W_IN 128

__device__ __forceinline__ float top2mean(float v0, float v1, float v2, float v3) {
    // sum of top-2 = total - (smallest) - (second smallest)
    float a = fminf(v0, v1), b = fmaxf(v0, v1);
    float c = fminf(v2, v3), d = fmaxf(v2, v3);
    float lo1 = fminf(a, c);                       // smallest
    float lo2 = fminf(fmaxf(a, c), fminf(b, d));   // second smallest
    return (v0 + v1 + v2 + v3 - lo1 - lo2) * 0.5f;
}

__global__ void __launch_bounds__(256)
rank_pool_kernel(const float4* __restrict__ in, float4* __restrict__ out, int n4) {
    int idx = blockIdx.x * blockDim.x + threadIdx.x;
    if (idx >= n4) return;

    // idx -> (b, ho, wo, c4)
    int c4 = idx & (C4 - 1);
    int t  = idx >> 6;               // /C4
    int wo = t & (WO - 1);
    t >>= 6;
    int ho = t & (HO - 1);
    int b  = t >> 6;

    // input row base in float4 units: ((b*128 + 2*ho)*128 + 2*wo)*64 + c4
    long base = (((long)(b * 128 + 2 * ho) * W_IN) + 2 * wo) * C4 + c4;
    const long ROW = (long)W_IN * C4;   // 8192 float4 per input row
    const long COL = C4;                // 64 float4 per pixel

    float4 p00 = in[base];
    float4 p01 = in[base + COL];
    float4 p10 = in[base + ROW];
    float4 p11 = in[base + ROW + COL];

    float4 r;
    r.x = top2mean(p00.x, p01.x, p10.x, p11.x);
    r.y = top2mean(p00.y, p01.y, p10.y, p11.y);
    r.z = top2mean(p00.z, p01.z, p10.z, p11.z);
    r.w = top2mean(p00.w, p01.w, p10.w, p11.w);

    out[idx] = r;
}

extern "C" void kernel_launch(void* const* d_in, const int* in_sizes, int n_in,
                              void* d_out, int out_size) {
    const float4* x = (const float4*)d_in[0];
    float4* o = (float4*)d_out;
    int n4 = out_size / 4;                 // 16*64*64*256 / 4 = 4,194,304
    int threads = 256;
    int blocks = (n4 + threads - 1) / threads;   // 16384
    rank_pool_kernel<<<blocks, threads>>>(x, o, n4);
}